// round 2
// baseline (speedup 1.0000x reference)
#include <cuda_runtime.h>
#include <cstdint>

// ---------------------------------------------------------------------------
// MSAttention: the reference's einsum 'bkhwlm,bkhwlnf->bkhwlf' factorizes as
// (sum_m A)*(sum_n V) = 1 * sum_n V, so attention is dead code. Output is a
// sum of V-projections of pooled inputs:
//   out0 (8,16,16,256) = Wvkid0*pool2(x1) + up4( Wvpeer0*pool4(x0) )
//   out1 (8,32,32,256) = Wvkid1*pool2(x2) + up2( Wvpeer1*pool2(x1) + Wvpar1*x0 )
//   out2 (8,64,64,256) =                    up2( Wvpeer2*pool2(x2) + Wvpar2*x1 )
// Wv* = rows [256,512) of the kv weights (pool = block SUM, not mean).
// ---------------------------------------------------------------------------

__device__ float g_P0[8 * 4 * 4 * 256];     // pool4(x0)
__device__ float g_Pa[8 * 16 * 16 * 256];   // pool2(x1)
__device__ float g_Pb[8 * 32 * 32 * 256];   // pool2(x2)

// ---------------------------------------------------------------------------
// Pooling: out[b,p,q,c] = sum over f x f input block. Vectorized float4 on c.
// ---------------------------------------------------------------------------
__global__ void pool_kernel(const float* __restrict__ in, float* __restrict__ out,
                            int Hc, int Wc, int f, int total4) {
    int i = blockIdx.x * blockDim.x + threadIdx.x;
    if (i >= total4) return;
    int c4 = i & 63;
    int r = i >> 6;
    int q = r % Wc; r /= Wc;
    int p = r % Hc;
    int b = r / Hc;
    int Win = Wc * f;
    const float4* in4 = (const float4*)in;
    float4 s = make_float4(0.f, 0.f, 0.f, 0.f);
    for (int dy = 0; dy < f; ++dy) {
        for (int dx = 0; dx < f; ++dx) {
            float4 v = in4[(size_t)((b * Hc * f + p * f + dy) * Win + q * f + dx) * 64 + c4];
            s.x += v.x; s.y += v.y; s.z += v.z; s.w += v.w;
        }
    }
    ((float4*)out)[i] = s;
}

// ---------------------------------------------------------------------------
// f32x2 helpers (packed dual-FMA: ptxas never emits these from plain C++)
// ---------------------------------------------------------------------------
__device__ __forceinline__ unsigned long long dupf(float x) {
    unsigned long long r;
    unsigned int u = __float_as_uint(x);
    asm("mov.b64 %0, {%1, %1};" : "=l"(r) : "r"(u));
    return r;
}
__device__ __forceinline__ void fma2(unsigned long long& d, unsigned long long a,
                                     unsigned long long b) {
    asm("fma.rn.f32x2 %0, %1, %2, %0;" : "+l"(d) : "l"(a), "l"(b));
}
__device__ __forceinline__ float f2lo(unsigned long long v) {
    return __uint_as_float((unsigned int)(v & 0xffffffffull));
}
__device__ __forceinline__ float f2hi(unsigned long long v) {
    return __uint_as_float((unsigned int)(v >> 32));
}

// ---------------------------------------------------------------------------
// GEMM: out[m, n] = sum_k A1[m,k]*W1[n,k] (+ A2[m,k]*W2[n,k] if A2 != null)
// A: [M, 256] row-major, W: [256, 256] row-major ([out,in] torch layout).
// Tile: BM=128, BN=64, BK=16, 256 threads, 8x4 per-thread microtile using
// fma.rn.f32x2 packed over the m-pairs.
// Epilogue MODE: 0 = store at row m; 1/2 = nearest-neighbor upsample by F
//   from coarse grid (Hc,Wc) per batch, 1 = write, 2 = read-add-write.
// M must be a multiple of 128 (it is: 128 / 2048 / 8192).
// ---------------------------------------------------------------------------
template <int MODE, int F>
__global__ void __launch_bounds__(256)
gemm_kernel(const float* __restrict__ A1, const float* __restrict__ W1,
            const float* __restrict__ A2, const float* __restrict__ W2,
            float* __restrict__ out, int Hc, int Wc) {
    __shared__ float As[16][128];
    __shared__ float Bs[16][64];

    const int t = threadIdx.x;
    const int tn = t & 15;        // 16 threads over n
    const int tm = t >> 4;        // 16 threads over m
    const int m0 = blockIdx.y * 128;
    const int n0 = blockIdx.x * 64;

    unsigned long long acc[4][4];  // m-pairs (2p,2p+1) x n(j)
#pragma unroll
    for (int p = 0; p < 4; ++p)
#pragma unroll
        for (int j = 0; j < 4; ++j) acc[p][j] = 0ull;

    const int ar = t >> 2;          // 0..63
    const int ak = (t & 3) << 2;    // 0,4,8,12

#pragma unroll 1
    for (int s = 0; s < 2; ++s) {
        const float* A = s ? A2 : A1;
        const float* W = s ? W2 : W1;
        if (A == nullptr) break;
#pragma unroll 1
        for (int k0 = 0; k0 < 256; k0 += 16) {
            float4 av0 = *(const float4*)&A[(size_t)(m0 + ar) * 256 + k0 + ak];
            float4 av1 = *(const float4*)&A[(size_t)(m0 + ar + 64) * 256 + k0 + ak];
            float4 bv  = *(const float4*)&W[(size_t)(n0 + ar) * 256 + k0 + ak];
            __syncthreads();
            As[ak + 0][ar] = av0.x; As[ak + 1][ar] = av0.y;
            As[ak + 2][ar] = av0.z; As[ak + 3][ar] = av0.w;
            As[ak + 0][ar + 64] = av1.x; As[ak + 1][ar + 64] = av1.y;
            As[ak + 2][ar + 64] = av1.z; As[ak + 3][ar + 64] = av1.w;
            Bs[ak + 0][ar] = bv.x; Bs[ak + 1][ar] = bv.y;
            Bs[ak + 2][ar] = bv.z; Bs[ak + 3][ar] = bv.w;
            __syncthreads();
#pragma unroll
            for (int k = 0; k < 16; ++k) {
                ulonglong2 a01 = *(const ulonglong2*)&As[k][tm * 8];
                ulonglong2 a23 = *(const ulonglong2*)&As[k][tm * 8 + 4];
                float4 bf = *(const float4*)&Bs[k][tn * 4];
                unsigned long long b0 = dupf(bf.x), b1 = dupf(bf.y);
                unsigned long long b2 = dupf(bf.z), b3 = dupf(bf.w);
                fma2(acc[0][0], a01.x, b0); fma2(acc[0][1], a01.x, b1);
                fma2(acc[0][2], a01.x, b2); fma2(acc[0][3], a01.x, b3);
                fma2(acc[1][0], a01.y, b0); fma2(acc[1][1], a01.y, b1);
                fma2(acc[1][2], a01.y, b2); fma2(acc[1][3], a01.y, b3);
                fma2(acc[2][0], a23.x, b0); fma2(acc[2][1], a23.x, b1);
                fma2(acc[2][2], a23.x, b2); fma2(acc[2][3], a23.x, b3);
                fma2(acc[3][0], a23.y, b0); fma2(acc[3][1], a23.y, b1);
                fma2(acc[3][2], a23.y, b2); fma2(acc[3][3], a23.y, b3);
            }
        }
    }

    // Epilogue
    const int nbase = n0 + tn * 4;
#pragma unroll
    for (int i = 0; i < 8; ++i) {
        const int p = i >> 1;
        float4 v;
        if ((i & 1) == 0) {
            v = make_float4(f2lo(acc[p][0]), f2lo(acc[p][1]), f2lo(acc[p][2]), f2lo(acc[p][3]));
        } else {
            v = make_float4(f2hi(acc[p][0]), f2hi(acc[p][1]), f2hi(acc[p][2]), f2hi(acc[p][3]));
        }
        const int m = m0 + tm * 8 + i;
        if (MODE == 0) {
            *(float4*)&out[(size_t)m * 256 + nbase] = v;
        } else {
            const int HW = Hc * Wc;
            const int b = m / HW;
            const int rem = m - b * HW;
            const int pY = rem / Wc;
            const int qX = rem - pY * Wc;
            const int Wf = Wc * F;
#pragma unroll
            for (int dy = 0; dy < F; ++dy) {
#pragma unroll
                for (int dx = 0; dx < F; ++dx) {
                    size_t fm = (size_t)(b * Hc * F + pY * F + dy) * Wf + (qX * F + dx);
                    float* dst = &out[fm * 256 + nbase];
                    if (MODE == 1) {
                        *(float4*)dst = v;
                    } else {
                        float4 o = *(const float4*)dst;
                        o.x += v.x; o.y += v.y; o.z += v.z; o.w += v.w;
                        *(float4*)dst = o;
                    }
                }
            }
        }
    }
}

// ---------------------------------------------------------------------------
// Launch
// ---------------------------------------------------------------------------
extern "C" void kernel_launch(void* const* d_in, const int* in_sizes, int n_in,
                              void* d_out, int out_size) {
    (void)n_in; (void)out_size;

    const float* x0 = (const float*)d_in[0];   // [8,16,16,256]
    const float* x1 = (const float*)d_in[1];   // [8,32,32,256]
    const float* x2 = (const float*)d_in[2];   // [8,64,64,256]

    // setup_inputs() builds the dict INTERLEAVED (qpeer_w0, kvpeer_w0,
    // qpeer_w1, kvpeer_w1, ...). Disambiguate by element count: kv weights
    // are 512*256 = 131072, q weights are 256*256 = 65536.
    const bool interleaved = (in_sizes[4] == 2 * 256 * 256);
    const float* kvpeer0 = (const float*)d_in[interleaved ? 4  : 6];
    const float* kvpeer1 = (const float*)d_in[interleaved ? 6  : 7];
    const float* kvpeer2 = (const float*)d_in[interleaved ? 8  : 8];
    const float* kvpar1  = (const float*)d_in[interleaved ? 10 : 11];
    const float* kvpar2  = (const float*)d_in[interleaved ? 12 : 12];
    const float* kvkid0  = (const float*)d_in[interleaved ? 14 : 15];
    const float* kvkid1  = (const float*)d_in[interleaved ? 16 : 16];
    const int VOFF = 256 * 256;  // V half = rows [256,512)

    float *P0, *Pa, *Pb;
    cudaGetSymbolAddress((void**)&P0, g_P0);
    cudaGetSymbolAddress((void**)&Pa, g_Pa);
    cudaGetSymbolAddress((void**)&Pb, g_Pb);

    float* out0 = (float*)d_out;                 // 8*16*16*256
    float* out1 = out0 + 8 * 16 * 16 * 256;      // 8*32*32*256
    float* out2 = out1 + 8 * 32 * 32 * 256;      // 8*64*64*256

    // Pools
    pool_kernel<<<32, 256>>>(x0, P0, 4, 4, 4, 8 * 4 * 4 * 64);
    pool_kernel<<<512, 256>>>(x1, Pa, 16, 16, 2, 8 * 16 * 16 * 64);
    pool_kernel<<<2048, 256>>>(x2, Pb, 32, 32, 2, 8 * 32 * 32 * 64);

    // Scale 0: out0 = Pa @ WvKid0^T  then  += up4(P0 @ WvPeer0^T)
    gemm_kernel<0, 1><<<dim3(4, 16), 256>>>(Pa, kvkid0 + VOFF, nullptr, nullptr, out0, 1, 1);
    gemm_kernel<2, 4><<<dim3(4, 1), 256>>>(P0, kvpeer0 + VOFF, nullptr, nullptr, out0, 4, 4);

    // Scale 1: out1 = Pb @ WvKid1^T  then  += up2(Pa @ WvPeer1^T + x0 @ WvPar1^T)
    gemm_kernel<0, 1><<<dim3(4, 64), 256>>>(Pb, kvkid1 + VOFF, nullptr, nullptr, out1, 1, 1);
    gemm_kernel<2, 2><<<dim3(4, 16), 256>>>(Pa, kvpeer1 + VOFF, x0, kvpar1 + VOFF, out1, 16, 16);

    // Scale 2: out2 = up2(Pb @ WvPeer2^T + x1 @ WvPar2^T)
    gemm_kernel<1, 2><<<dim3(4, 64), 256>>>(Pb, kvpeer2 + VOFF, x1, kvpar2 + VOFF, out2, 32, 32);
}